// round 12
// baseline (speedup 1.0000x reference)
#include <cuda_runtime.h>

#define NVERTS 2000000
#define NFACES 4000000
#define NPAIRS (NFACES/2)
#define NITERS 10
#define DT 1e-8f
#define BULK 2500.0f
#define M21 ((1ull<<21)-1ull)
#define TPB 192
#define BPSM 6
#define GRID_P (148*BPSM)   // 888 blocks, 6/SM co-resident (56 regs cap, no spill)
#define NWARP (TPB/32)

// Scratch (device globals: allocation-free per harness rules)
__device__ float4 g_x[2][NVERTS];                 // double-buffered vertices (64 MB)
__device__ unsigned long long g_fp[NFACES];       // packed 3x21-bit indices (32 MB)
__device__ double g_vol;
__device__ float g_p;
__device__ unsigned int g_bar_cnt;
__device__ volatile unsigned int g_bar_gen;

__device__ __forceinline__ void red4(float4* p, float x, float y, float z) {
    asm volatile("red.global.add.v4.f32 [%0], {%1, %2, %3, %4};"
                 :: "l"(p), "f"(x), "f"(y), "f"(z), "f"(0.0f) : "memory");
}

__device__ __forceinline__ float det3(float4 a, float4 b, float4 c) {
    return a.x * (b.y * c.z - b.z * c.y)
         + a.y * (b.z * c.x - b.x * c.z)
         + a.z * (b.x * c.y - b.y * c.x);
}

// Grid-wide barrier; the LAST arriving block optionally finalizes p.
__device__ __forceinline__ void grid_barrier(bool compute_p) {
    __syncthreads();
    if (threadIdx.x == 0) {
        unsigned gen = g_bar_gen;
        __threadfence();                                  // order REDG/atomics
        unsigned t = atomicAdd(&g_bar_cnt, 1u);
        if (t == GRID_P - 1u) {
            if (compute_p) {
                double vol = g_vol * (1.0 / 6.0);
                float stv = expf(0.04f);                  // exp(PRESSURE0/BULK)
                g_p = BULK * (stv - (float)vol) / stv;
                g_vol = 0.0;
            }
            g_bar_cnt = 0u;
            __threadfence();
            g_bar_gen = gen + 1u;                         // release
        } else {
            while (g_bar_gen == gen) __nanosleep(32);
            __threadfence();                              // acquire
        }
    }
    __syncthreads();
}

// ---------- prologue ----------

__global__ void __launch_bounds__(256) k_init(const float* __restrict__ v,
                                              const void* __restrict__ fraw) {
    int i = blockIdx.x * 256 + threadIdx.x;

    const long long* f64 = (const long long*)fraw;
    const int* f32 = (const int*)fraw;
    bool is64 = true;
    #pragma unroll
    for (int k = 0; k < 8; k++)
        if ((unsigned long long)__ldg(&f64[k]) >= (unsigned long long)NVERTS) is64 = false;

    if (i < NFACES) {
        unsigned long long a, b, c;
        if (is64) {
            a = (unsigned long long)__ldg(&f64[3*i+0]);
            b = (unsigned long long)__ldg(&f64[3*i+1]);
            c = (unsigned long long)__ldg(&f64[3*i+2]);
        } else {
            a = (unsigned long long)(unsigned int)__ldg(&f32[3*i+0]);
            b = (unsigned long long)(unsigned int)__ldg(&f32[3*i+1]);
            c = (unsigned long long)(unsigned int)__ldg(&f32[3*i+2]);
        }
        g_fp[i] = a | (b << 21) | (c << 42);
    }
    if (i < NVERTS) g_x[0][i] = make_float4(v[3*i], v[3*i+1], v[3*i+2], 0.0f);
    if (i == 0) { g_vol = 0.0; g_bar_cnt = 0u; g_bar_gen = 0u; }
}

// One face's force contribution, scattered dt-scaled into xd.
__device__ __forceinline__ void face_force(const float4* __restrict__ xs,
                                           float4* xd, unsigned long long f,
                                           float q, float s) {
    int i0 = (int)(f & M21), i1 = (int)((f >> 21) & M21), i2 = (int)(f >> 42);
    float4 a = __ldg(&xs[i0]);
    float4 b = __ldg(&xs[i1]);
    float4 c = __ldg(&xs[i2]);

    float e1x = b.x - a.x, e1y = b.y - a.y, e1z = b.z - a.z;
    float e2x = c.x - a.x, e2y = c.y - a.y, e2z = c.z - a.z;
    float nx = e1y * e2z - e1z * e2y;
    float ny = e1z * e2x - e1x * e2z;
    float nz = e1x * e2y - e1y * e2x;
    float inv = 1.0f / (sqrtf(nx*nx + ny*ny + nz*nz) + 1e-12f);
    float hx = nx * inv, hy = ny * inv, hz = nz * inv;

    float d0x = c.x - b.x, d0y = c.y - b.y, d0z = c.z - b.z;
    float g0x = q * (b.y*c.z - b.z*c.y) - s * (hy*d0z - hz*d0y);
    float g0y = q * (b.z*c.x - b.x*c.z) - s * (hz*d0x - hx*d0z);
    float g0z = q * (b.x*c.y - b.y*c.x) - s * (hx*d0y - hy*d0x);
    float d1x = a.x - c.x, d1y = a.y - c.y, d1z = a.z - c.z;
    float g1x = q * (c.y*a.z - c.z*a.y) - s * (hy*d1z - hz*d1y);
    float g1y = q * (c.z*a.x - c.x*a.z) - s * (hz*d1x - hx*d1z);
    float g1z = q * (c.x*a.y - c.y*a.x) - s * (hx*d1y - hy*d1x);
    float g2x = q * (a.y*b.z - a.z*b.y) - s * (hy*e1z - hz*e1y);
    float g2y = q * (a.z*b.x - a.x*b.z) - s * (hz*e1x - hx*e1z);
    float g2z = q * (a.x*b.y - a.y*b.x) - s * (hx*e1y - hy*e1x);

    red4(&xd[i0], g0x, g0y, g0z);
    red4(&xd[i1], g1x, g1y, g1z);
    red4(&xd[i2], g2x, g2y, g2z);
}

// ---------- persistent iteration kernel (all 10 iterations, 20 barriers) ----------

__global__ void __launch_bounds__(TPB, BPSM) k_iter() {
    const int T = GRID_P * TPB;                    // 170496 threads
    const int gid = blockIdx.x * TPB + threadIdx.x;
    const ulonglong2* __restrict__ fp2 = (const ulonglong2*)g_fp;

    int src = 0;
    for (int it = 0; it < NITERS; it++) {
        const float4* __restrict__ xs = g_x[src];
        float4* __restrict__ xd = g_x[src ^ 1];

        // Phase A1: copy x -> x' (coalesced grid-stride)
        for (int v = gid; v < NVERTS; v += T)
            xd[v] = __ldg(&xs[v]);

        // Phase A2: det reduction, 2 pairs (4 faces, 12 gathers) per step.
        // Out-of-range pair padded with face (0,0,0): det3(x0,x0,x0) == 0 exactly.
        float det = 0.0f;
        for (int j = gid; j < NPAIRS; j += 2*T) {
            int j2 = j + T;
            ulonglong2 fA = __ldg(fp2 + j);
            ulonglong2 fB = (j2 < NPAIRS) ? __ldg(fp2 + j2) : make_ulonglong2(0ull, 0ull);
            int a0=(int)(fA.x&M21), a1=(int)((fA.x>>21)&M21), a2=(int)(fA.x>>42);
            int b0=(int)(fA.y&M21), b1=(int)((fA.y>>21)&M21), b2=(int)(fA.y>>42);
            int c0=(int)(fB.x&M21), c1=(int)((fB.x>>21)&M21), c2=(int)(fB.x>>42);
            int d0=(int)(fB.y&M21), d1=(int)((fB.y>>21)&M21), d2=(int)(fB.y>>42);
            float4 A0=__ldg(&xs[a0]), A1=__ldg(&xs[a1]), A2=__ldg(&xs[a2]);
            float4 B0=__ldg(&xs[b0]), B1=__ldg(&xs[b1]), B2=__ldg(&xs[b2]);
            float4 C0=__ldg(&xs[c0]), C1=__ldg(&xs[c1]), C2=__ldg(&xs[c2]);
            float4 D0=__ldg(&xs[d0]), D1=__ldg(&xs[d1]), D2=__ldg(&xs[d2]);
            det += (det3(A0,A1,A2) + det3(B0,B1,B2))
                 + (det3(C0,C1,C2) + det3(D0,D1,D2));
        }

        // block-level reduce -> g_vol
        #pragma unroll
        for (int o = 16; o > 0; o >>= 1) det += __shfl_down_sync(0xffffffffu, det, o);
        __shared__ float ws[NWARP];
        if ((threadIdx.x & 31) == 0) ws[threadIdx.x >> 5] = det;
        __syncthreads();
        if (threadIdx.x == 0) {
            double sd = 0.0;
            #pragma unroll
            for (int k = 0; k < NWARP; k++) sd += (double)ws[k];
            atomicAdd(&g_vol, sd);
        }

        grid_barrier(true);                        // last arrival computes exact p

        // Phase B: forces with exact p, 1 pair (2 faces) per step.
        float q = g_p * (DT / 6.0f);               // dt * p * (cross/6)
        const float s = 0.5f * DT;                 // dt * SURFACE_TENSION * 0.5
        for (int j = gid; j < NPAIRS; j += T) {
            ulonglong2 f = __ldg(fp2 + j);
            face_force(xs, xd, f.x, q, s);
            face_force(xs, xd, f.y, q, s);
        }

        grid_barrier(false);                       // all REDGs visible before next iter
        src ^= 1;
    }
}

// Final: unpad into d_out.
__global__ void __launch_bounds__(256) k_pack(float* __restrict__ out, int src) {
    int i = blockIdx.x * 256 + threadIdx.x;
    if (i < NVERTS) {
        float4 v = g_x[src][i];
        out[3*i] = v.x; out[3*i+1] = v.y; out[3*i+2] = v.z;
    }
}

extern "C" void kernel_launch(void* const* d_in, const int* in_sizes, int n_in,
                              void* d_out, int out_size) {
    const float* verts;
    const void* faces;
    if (in_sizes[0] == 3 * NVERTS) { verts = (const float*)d_in[0]; faces = d_in[1]; }
    else                           { verts = (const float*)d_in[1]; faces = d_in[0]; }

    const int FB = NFACES / 256;                   // 15625
    const int CB = (NVERTS + 255) / 256;

    k_init<<<FB, 256>>>(verts, faces);
    k_iter<<<GRID_P, TPB>>>();                     // all 10 iterations, persistent
    k_pack<<<CB, 256>>>((float*)d_out, NITERS & 1);
}

// round 13
// speedup vs baseline: 1.0237x; 1.0237x over previous
#include <cuda_runtime.h>

#define NVERTS 2000000
#define NFACES 4000000
#define NPAIRS (NFACES/2)
#define NITERS 10
#define DT 1e-8f
#define BULK 2500.0f
#define M21 ((1ull<<21)-1ull)
#define GRID_P 592          // 4 blocks/SM on 148 SMs — co-resident guaranteed
#define TPB 256

// Scratch (device globals: allocation-free per harness rules)
__device__ float4 g_x[2][NVERTS];                 // double-buffered vertices (64 MB)
__device__ unsigned long long g_fp[NFACES];       // packed 3x21-bit indices (32 MB)
__device__ double g_vol;
__device__ float g_p;
__device__ unsigned int g_bar_cnt;
__device__ volatile unsigned int g_bar_gen;

__device__ __forceinline__ void red4(float4* p, float x, float y, float z) {
    asm volatile("red.global.add.v4.f32 [%0], {%1, %2, %3, %4};"
                 :: "l"(p), "f"(x), "f"(y), "f"(z), "f"(0.0f) : "memory");
}

__device__ __forceinline__ float det3(float4 a, float4 b, float4 c) {
    return a.x * (b.y * c.z - b.z * c.y)
         + a.y * (b.z * c.x - b.x * c.z)
         + a.z * (b.x * c.y - b.y * c.x);
}

// Grid-wide barrier; the LAST arriving block optionally finalizes p.
__device__ __forceinline__ void grid_barrier(bool compute_p) {
    __syncthreads();
    if (threadIdx.x == 0) {
        unsigned gen = g_bar_gen;
        __threadfence();                                  // order REDG/atomics
        unsigned t = atomicAdd(&g_bar_cnt, 1u);
        if (t == GRID_P - 1u) {
            if (compute_p) {
                double vol = g_vol * (1.0 / 6.0);
                float stv = expf(0.04f);                  // exp(PRESSURE0/BULK)
                g_p = BULK * (stv - (float)vol) / stv;
                g_vol = 0.0;
            }
            g_bar_cnt = 0u;
            __threadfence();
            g_bar_gen = gen + 1u;                         // release
        } else {
            while (g_bar_gen == gen) __nanosleep(64);
            __threadfence();                              // acquire
        }
    }
    __syncthreads();
}

// ---------- prologue ----------

// Pack faces (auto int32/int64) at 2 faces/thread with vector loads;
// seed x[0] (1 vert/thread); zero accumulators.
__global__ void __launch_bounds__(256) k_init(const float* __restrict__ v,
                                              const void* __restrict__ fraw) {
    int i = blockIdx.x * 256 + threadIdx.x;       // pair index / vertex index

    // dtype probe (broadcast, L1-resident): true int64 indices all < NVERTS;
    // int32 data read as int64 has high half = next random index (>= 2^32).
    const long long* f64 = (const long long*)fraw;
    bool is64 = true;
    #pragma unroll
    for (int k = 0; k < 8; k++)
        if ((unsigned long long)__ldg(&f64[k]) >= (unsigned long long)NVERTS) is64 = false;

    if (i < NPAIRS) {
        unsigned long long a0, a1, a2, b0, b1, b2;
        if (is64) {
            // 2 faces = 6 longs = 3x ulonglong2 (16B-aligned: 48B pair stride)
            const ulonglong2* f2 = (const ulonglong2*)fraw;
            ulonglong2 q0 = __ldg(&f2[3*i+0]);
            ulonglong2 q1 = __ldg(&f2[3*i+1]);
            ulonglong2 q2 = __ldg(&f2[3*i+2]);
            a0 = q0.x; a1 = q0.y; a2 = q1.x;
            b0 = q1.y; b1 = q2.x; b2 = q2.y;
        } else {
            // 2 faces = 6 ints = 3x int2 (8B-aligned)
            const int2* f2 = (const int2*)fraw;
            int2 q0 = __ldg(&f2[3*i+0]);
            int2 q1 = __ldg(&f2[3*i+1]);
            int2 q2 = __ldg(&f2[3*i+2]);
            a0 = (unsigned int)q0.x; a1 = (unsigned int)q0.y; a2 = (unsigned int)q1.x;
            b0 = (unsigned int)q1.y; b1 = (unsigned int)q2.x; b2 = (unsigned int)q2.y;
        }
        g_fp[2*i]   = a0 | (a1 << 21) | (a2 << 42);
        g_fp[2*i+1] = b0 | (b1 << 21) | (b2 << 42);
    }
    if (i < NVERTS) g_x[0][i] = make_float4(v[3*i], v[3*i+1], v[3*i+2], 0.0f);
    if (i == 0) { g_vol = 0.0; g_bar_cnt = 0u; g_bar_gen = 0u; }
}

// One face's force contribution, scattered dt-scaled into xd.
__device__ __forceinline__ void face_force(const float4* __restrict__ xs,
                                           float4* xd, unsigned long long f,
                                           float q, float s) {
    int i0 = (int)(f & M21), i1 = (int)((f >> 21) & M21), i2 = (int)(f >> 42);
    float4 a = __ldg(&xs[i0]);
    float4 b = __ldg(&xs[i1]);
    float4 c = __ldg(&xs[i2]);

    float e1x = b.x - a.x, e1y = b.y - a.y, e1z = b.z - a.z;
    float e2x = c.x - a.x, e2y = c.y - a.y, e2z = c.z - a.z;
    float nx = e1y * e2z - e1z * e2y;
    float ny = e1z * e2x - e1x * e2z;
    float nz = e1x * e2y - e1y * e2x;
    float inv = 1.0f / (sqrtf(nx*nx + ny*ny + nz*nz) + 1e-12f);
    float hx = nx * inv, hy = ny * inv, hz = nz * inv;

    float d0x = c.x - b.x, d0y = c.y - b.y, d0z = c.z - b.z;
    float g0x = q * (b.y*c.z - b.z*c.y) - s * (hy*d0z - hz*d0y);
    float g0y = q * (b.z*c.x - b.x*c.z) - s * (hz*d0x - hx*d0z);
    float g0z = q * (b.x*c.y - b.y*c.x) - s * (hx*d0y - hy*d0x);
    float d1x = a.x - c.x, d1y = a.y - c.y, d1z = a.z - c.z;
    float g1x = q * (c.y*a.z - c.z*a.y) - s * (hy*d1z - hz*d1y);
    float g1y = q * (c.z*a.x - c.x*a.z) - s * (hz*d1x - hx*d1z);
    float g1z = q * (c.x*a.y - c.y*a.x) - s * (hx*d1y - hy*d1x);
    float g2x = q * (a.y*b.z - a.z*b.y) - s * (hy*e1z - hz*e1y);
    float g2y = q * (a.z*b.x - a.x*b.z) - s * (hz*e1x - hx*e1z);
    float g2z = q * (a.x*b.y - a.y*b.x) - s * (hx*e1y - hy*e1x);

    red4(&xd[i0], g0x, g0y, g0z);
    red4(&xd[i1], g1x, g1y, g1z);
    red4(&xd[i2], g2x, g2y, g2z);
}

// ---------- persistent iteration kernel (all 10 iterations, 20 barriers) ----------

__global__ void __launch_bounds__(TPB, 4) k_iter() {
    const int T = GRID_P * TPB;                    // 151552 threads
    const int gid = blockIdx.x * TPB + threadIdx.x;
    const ulonglong2* __restrict__ fp2 = (const ulonglong2*)g_fp;

    int src = 0;
    for (int it = 0; it < NITERS; it++) {
        const float4* __restrict__ xs = g_x[src];
        float4* __restrict__ xd = g_x[src ^ 1];

        // Phase A1: copy x -> x' (coalesced grid-stride)
        for (int v = gid; v < NVERTS; v += T)
            xd[v] = __ldg(&xs[v]);

        // Phase A2: det reduction, 2 pairs (4 faces, 12 gathers) per step.
        // Out-of-range pair padded with face (0,0,0): det3(x0,x0,x0) == 0 exactly.
        float det = 0.0f;
        for (int j = gid; j < NPAIRS; j += 2*T) {
            int j2 = j + T;
            ulonglong2 fA = __ldg(fp2 + j);
            ulonglong2 fB = (j2 < NPAIRS) ? __ldg(fp2 + j2) : make_ulonglong2(0ull, 0ull);
            int a0=(int)(fA.x&M21), a1=(int)((fA.x>>21)&M21), a2=(int)(fA.x>>42);
            int b0=(int)(fA.y&M21), b1=(int)((fA.y>>21)&M21), b2=(int)(fA.y>>42);
            int c0=(int)(fB.x&M21), c1=(int)((fB.x>>21)&M21), c2=(int)(fB.x>>42);
            int d0=(int)(fB.y&M21), d1=(int)((fB.y>>21)&M21), d2=(int)(fB.y>>42);
            float4 A0=__ldg(&xs[a0]), A1=__ldg(&xs[a1]), A2=__ldg(&xs[a2]);
            float4 B0=__ldg(&xs[b0]), B1=__ldg(&xs[b1]), B2=__ldg(&xs[b2]);
            float4 C0=__ldg(&xs[c0]), C1=__ldg(&xs[c1]), C2=__ldg(&xs[c2]);
            float4 D0=__ldg(&xs[d0]), D1=__ldg(&xs[d1]), D2=__ldg(&xs[d2]);
            det += (det3(A0,A1,A2) + det3(B0,B1,B2))
                 + (det3(C0,C1,C2) + det3(D0,D1,D2));
        }

        // block-level reduce -> g_vol
        #pragma unroll
        for (int o = 16; o > 0; o >>= 1) det += __shfl_down_sync(0xffffffffu, det, o);
        __shared__ float ws[8];
        if ((threadIdx.x & 31) == 0) ws[threadIdx.x >> 5] = det;
        __syncthreads();
        if (threadIdx.x == 0) {
            double sd = 0.0;
            #pragma unroll
            for (int k = 0; k < 8; k++) sd += (double)ws[k];
            atomicAdd(&g_vol, sd);
        }

        grid_barrier(true);                        // last arrival computes exact p

        // Phase B: forces with exact p, 1 pair (2 faces) per step.
        float q = g_p * (DT / 6.0f);               // dt * p * (cross/6)
        const float s = 0.5f * DT;                 // dt * SURFACE_TENSION * 0.5
        for (int j = gid; j < NPAIRS; j += T) {
            ulonglong2 f = __ldg(fp2 + j);
            face_force(xs, xd, f.x, q, s);
            face_force(xs, xd, f.y, q, s);
        }

        grid_barrier(false);                       // all REDGs visible before next iter
        src ^= 1;
    }
}

// Final: unpad into d_out.
__global__ void __launch_bounds__(256) k_pack(float* __restrict__ out, int src) {
    int i = blockIdx.x * 256 + threadIdx.x;
    if (i < NVERTS) {
        float4 v = g_x[src][i];
        out[3*i] = v.x; out[3*i+1] = v.y; out[3*i+2] = v.z;
    }
}

extern "C" void kernel_launch(void* const* d_in, const int* in_sizes, int n_in,
                              void* d_out, int out_size) {
    const float* verts;
    const void* faces;
    if (in_sizes[0] == 3 * NVERTS) { verts = (const float*)d_in[0]; faces = d_in[1]; }
    else                           { verts = (const float*)d_in[1]; faces = d_in[0]; }

    const int IB = (NPAIRS + 255) / 256;           // 7813: 2 faces/thread, 1 vert/thread
    const int CB = (NVERTS + 255) / 256;

    k_init<<<IB, 256>>>(verts, faces);
    k_iter<<<GRID_P, TPB>>>();                     // all 10 iterations, persistent
    k_pack<<<CB, 256>>>((float*)d_out, NITERS & 1);
}